// round 4
// baseline (speedup 1.0000x reference)
#include <cuda_runtime.h>
#include <cuda_bf16.h>

// Problem: out[b,q,d] = sum_k A[b,q,k] * V[b,k,d] / max(sum_k A[b,q,k], 1)
//          A = qm[b,q]*km[b,k] * exp( (Q.K^T)/sqrt(D) )
// B=8, L=2048, D=64, fp32.  Raw exp (no max-shift) is numerically safe here.

#define BQ    64          // q rows per block
#define BK    64          // k rows per tile
#define DIMD  64          // head dim
#define SST   68          // padded smem row stride (floats): odd*4 -> 16B aligned, low conflict
#define NB    8
#define SEQ   2048

__global__ __launch_bounds__(256, 2)
void attn77_kernel(const float* __restrict__ Q, const float* __restrict__ K,
                   const float* __restrict__ V, const int* __restrict__ QM,
                   const int* __restrict__ KM, float* __restrict__ O)
{
    extern __shared__ float smbuf[];
    float (*Qs)[SST]  = (float(*)[SST])(smbuf);                     // [d][q]
    float (*Ks)[SST]  = (float(*)[SST])(smbuf + 1 * DIMD * SST);    // [d][k]
    float (*Vs)[SST]  = (float(*)[SST])(smbuf + 2 * DIMD * SST);    // [k][d]
    float (*Ss)[SST]  = (float(*)[SST])(smbuf + 3 * DIMD * SST);    // [k][q] exp-scores
    float (*RSp)[17]  = (float(*)[17]) (smbuf + 4 * DIMD * SST);    // rowsum partials
    float* KMs = smbuf + 4 * DIMD * SST + BQ * 17;
    float* RSf = KMs + BK;
    float* QMs = RSf + BQ;

    const int tid = threadIdx.x;
    const int tx  = tid & 15;        // k / d micro-tile index (0..15)
    const int ty  = tid >> 4;        // q micro-tile index (0..15)
    const int b   = blockIdx.x >> 5; // 32 q-tiles per batch
    const int q0  = (blockIdx.x & 31) * BQ;

    const float* Qb = Q + ((size_t)b * SEQ + q0) * DIMD;
    const float* Kb = K + (size_t)b * SEQ * DIMD;
    const float* Vb = V + (size_t)b * SEQ * DIMD;

    // ---- Load Q tile, transposed to [d][q] for conflict-free float4 reads ----
    #pragma unroll
    for (int j = 0; j < 4; j++) {
        int i  = tid + j * 256;          // float4 index 0..1023
        int r  = i >> 4;                 // q row 0..63
        int c4 = (i & 15) << 2;          // d col (multiple of 4)
        float4 v = *reinterpret_cast<const float4*>(Qb + r * DIMD + c4);
        Qs[c4 + 0][r] = v.x; Qs[c4 + 1][r] = v.y;
        Qs[c4 + 2][r] = v.z; Qs[c4 + 3][r] = v.w;
    }
    if (tid < BQ) QMs[tid] = (float)QM[b * SEQ + q0 + tid];

    float acc[4][4] = {};
    float rs[4]     = {0.f, 0.f, 0.f, 0.f};

    for (int kt = 0; kt < SEQ; kt += BK) {
        __syncthreads();   // previous iteration's Ks/Vs/Ss reads are done

        // ---- Load K tile (transposed) and V tile (row-major) ----
        #pragma unroll
        for (int j = 0; j < 4; j++) {
            int i  = tid + j * 256;
            int r  = i >> 4;
            int c4 = (i & 15) << 2;
            float4 kv = *reinterpret_cast<const float4*>(Kb + (size_t)(kt + r) * DIMD + c4);
            Ks[c4 + 0][r] = kv.x; Ks[c4 + 1][r] = kv.y;
            Ks[c4 + 2][r] = kv.z; Ks[c4 + 3][r] = kv.w;
            float4 vv = *reinterpret_cast<const float4*>(Vb + (size_t)(kt + r) * DIMD + c4);
            *reinterpret_cast<float4*>(&Vs[r][c4]) = vv;
        }
        if (tid < BK) KMs[tid] = (float)KM[b * SEQ + kt + tid];
        __syncthreads();

        // ---- Stage 1: S = Q . K^T  (4q x 4k micro-tile per thread) ----
        float s[4][4] = {};
        #pragma unroll 16
        for (int d = 0; d < DIMD; d++) {
            float4 qf = *reinterpret_cast<const float4*>(&Qs[d][ty << 2]);
            float4 kf = *reinterpret_cast<const float4*>(&Ks[d][tx << 2]);
            s[0][0] += qf.x * kf.x; s[0][1] += qf.x * kf.y; s[0][2] += qf.x * kf.z; s[0][3] += qf.x * kf.w;
            s[1][0] += qf.y * kf.x; s[1][1] += qf.y * kf.y; s[1][2] += qf.y * kf.z; s[1][3] += qf.y * kf.w;
            s[2][0] += qf.z * kf.x; s[2][1] += qf.z * kf.y; s[2][2] += qf.z * kf.z; s[2][3] += qf.z * kf.w;
            s[3][0] += qf.w * kf.x; s[3][1] += qf.w * kf.y; s[3][2] += qf.w * kf.z; s[3][3] += qf.w * kf.w;
        }

        // ---- exp + k-mask + rowsum, store S_exp transposed [k][q] ----
        #pragma unroll
        for (int j = 0; j < 4; j++) {
            float kmv = KMs[(tx << 2) + j];
            #pragma unroll
            for (int i = 0; i < 4; i++) {
                float e = kmv * __expf(s[i][j] * 0.125f);   // 1/sqrt(64)
                rs[i] += e;
                Ss[(tx << 2) + j][(ty << 2) + i] = e;
            }
        }
        __syncthreads();

        // ---- Stage 2: acc += S_exp . V  (4q x 4d micro-tile) ----
        #pragma unroll 8
        for (int k = 0; k < BK; k++) {
            float4 sf = *reinterpret_cast<const float4*>(&Ss[k][ty << 2]);
            float4 vf = *reinterpret_cast<const float4*>(&Vs[k][tx << 2]);
            acc[0][0] += sf.x * vf.x; acc[0][1] += sf.x * vf.y; acc[0][2] += sf.x * vf.z; acc[0][3] += sf.x * vf.w;
            acc[1][0] += sf.y * vf.x; acc[1][1] += sf.y * vf.y; acc[1][2] += sf.y * vf.z; acc[1][3] += sf.y * vf.w;
            acc[2][0] += sf.z * vf.x; acc[2][1] += sf.z * vf.y; acc[2][2] += sf.z * vf.z; acc[2][3] += sf.z * vf.w;
            acc[3][0] += sf.w * vf.x; acc[3][1] += sf.w * vf.y; acc[3][2] += sf.w * vf.z; acc[3][3] += sf.w * vf.w;
        }
    }

    // ---- Reduce row sums across the 16 k-column threads ----
    #pragma unroll
    for (int i = 0; i < 4; i++) RSp[(ty << 2) + i][tx] = rs[i];
    __syncthreads();
    if (tid < BQ) {
        float t = 0.f;
        #pragma unroll
        for (int c = 0; c < 16; c++) t += RSp[tid][c];
        RSf[tid] = fmaxf(t, 1.0f);
    }
    __syncthreads();

    // ---- Epilogue: out = acc * qm / max(rowsum, 1) ----
    float* Ob = O + ((size_t)b * SEQ + q0) * DIMD;
    #pragma unroll
    for (int i = 0; i < 4; i++) {
        int qi = (ty << 2) + i;
        float inv = QMs[qi] / RSf[qi];   // 0 if q-masked
        float4 o;
        o.x = acc[i][0] * inv; o.y = acc[i][1] * inv;
        o.z = acc[i][2] * inv; o.w = acc[i][3] * inv;
        *reinterpret_cast<float4*>(Ob + qi * DIMD + (tx << 2)) = o;
    }
}

extern "C" void kernel_launch(void* const* d_in, const int* in_sizes, int n_in,
                              void* d_out, int out_size)
{
    const float* Q  = (const float*)d_in[0];
    const float* K  = (const float*)d_in[1];
    const float* V  = (const float*)d_in[2];
    const int*   QM = (const int*)d_in[3];
    const int*   KM = (const int*)d_in[4];
    float*       O  = (float*)d_out;

    const int smem_bytes = (4 * DIMD * SST + BQ * 17 + BK + 2 * BQ) * (int)sizeof(float); // 74752 B
    cudaFuncSetAttribute(attn77_kernel, cudaFuncAttributeMaxDynamicSharedMemorySize, smem_bytes);

    dim3 grid(NB * (SEQ / BQ));   // 8 * 32 = 256 blocks
    attn77_kernel<<<grid, 256, smem_bytes>>>(Q, K, V, QM, KM, O);
}

// round 6
// speedup vs baseline: 3.4948x; 3.4948x over previous
#include <cuda_runtime.h>
#include <cuda_bf16.h>
#include <cstdint>

// out[b,q,d] = qm[q] * (sum_k km[k]*exp(QK^T/8) V[k,d]) / max(rowsum,1)
// B=8, L=2048, D=64 fp32.  Legacy tensor path: mma.sync bf16 with hi/lo split
// (3-term) for both GEMMs; tcgen05 is unavailable (harness targets sm_103, not sm_103a).

#define SEQ  2048
#define HD   64
#define BQ   128
#define BK   128
#define NKT  (SEQ/BK)
#define KST  72                      // bf16 row stride for staged tiles (144B rows)

#define OFF_KM   0
#define OFF_KHI  1024
#define OFF_KLO  (OFF_KHI + BK*KST*2)      // 19456
#define OFF_VHI  (OFF_KLO + BK*KST*2)      // 37888
#define OFF_VLO  (OFF_VHI + BK*KST*2)      // 56320
#define SMEM_BYTES (OFF_VLO + BK*KST*2)    // 74752

__device__ __forceinline__ uint32_t smem_u32(const void* p) {
    uint32_t a;
    asm("{ .reg .u64 t; cvta.to.shared.u64 t, %1; cvt.u32.u64 %0, t; }" : "=r"(a) : "l"(p));
    return a;
}
// pack {lo, hi} floats into bf16x2 (lo in bits [0:16))
__device__ __forceinline__ uint32_t packbf(float lo, float hi) {
    uint32_t r;
    asm("cvt.rn.bf16x2.f32 %0, %1, %2;" : "=r"(r) : "f"(hi), "f"(lo));
    return r;
}
__device__ __forceinline__ float bflo(uint32_t p) { return __uint_as_float(p << 16); }
__device__ __forceinline__ float bfhi(uint32_t p) { return __uint_as_float(p & 0xffff0000u); }

__device__ __forceinline__ void mma16816(float c[4], const uint32_t a[4], const uint32_t b[2]) {
    asm volatile("mma.sync.aligned.m16n8k16.row.col.f32.bf16.bf16.f32 "
        "{%0,%1,%2,%3}, {%4,%5,%6,%7}, {%8,%9}, {%0,%1,%2,%3};"
        : "+f"(c[0]), "+f"(c[1]), "+f"(c[2]), "+f"(c[3])
        : "r"(a[0]), "r"(a[1]), "r"(a[2]), "r"(a[3]), "r"(b[0]), "r"(b[1]));
}
__device__ __forceinline__ void ldm2t(uint32_t& r0, uint32_t& r1, uint32_t addr) {
    asm volatile("ldmatrix.sync.aligned.m8n8.x2.trans.shared.b16 {%0,%1}, [%2];"
                 : "=r"(r0), "=r"(r1) : "r"(addr));
}

// split a float4 into bf16 hi + bf16 residual lo, store both as uint2
__device__ __forceinline__ void split_store(char* smem, int off_hi, int off_lo,
                                            int elem_off, float4 v) {
    uint32_t h01 = packbf(v.x, v.y), h23 = packbf(v.z, v.w);
    uint2 hh; hh.x = h01; hh.y = h23;
    *(uint2*)(smem + off_hi + elem_off * 2) = hh;
    uint2 ll;
    ll.x = packbf(v.x - bflo(h01), v.y - bfhi(h01));
    ll.y = packbf(v.z - bflo(h23), v.w - bfhi(h23));
    *(uint2*)(smem + off_lo + elem_off * 2) = ll;
}

__global__ __launch_bounds__(256, 1)
void attn77_mma(const float* __restrict__ Q, const float* __restrict__ K,
                const float* __restrict__ V, const int* __restrict__ QM,
                const int* __restrict__ KM, float* __restrict__ O)
{
    extern __shared__ char smem[];
    const uint32_t sb = smem_u32(smem);
    float* kms = (float*)(smem + OFF_KM);

    const int tid  = threadIdx.x;
    const int wid  = tid >> 5, lane = tid & 31;
    const int g    = lane >> 2, t = lane & 3;
    const int b    = blockIdx.x >> 4;
    const int q0   = (blockIdx.x & 15) * BQ;
    const int r0   = wid * 16;                 // warp's q rows [r0, r0+16)

    const float* Qb = Q + ((size_t)b * SEQ + q0) * HD;
    const float* Kb = K + (size_t)b * SEQ * HD;
    const float* Vb = V + (size_t)b * SEQ * HD;

    // ---- stage Q (split bf16 hi/lo) into the K region, extract A fragments ----
    #pragma unroll
    for (int j = 0; j < 8; j++) {
        int i = tid + j * 256;
        int r = i >> 4, c4 = (i & 15) << 2;
        float4 v = *(const float4*)(Qb + r * HD + c4);
        split_store(smem, OFF_KHI, OFF_KLO, r * KST + c4, v);
    }
    __syncthreads();

    uint32_t qh[4][4], ql[4][4];
    #pragma unroll
    for (int ks = 0; ks < 4; ks++) {
        int c0 = 16 * ks + 2 * t;
        qh[ks][0] = *(const uint32_t*)(smem + OFF_KHI + ((r0 + g)     * KST + c0)     * 2);
        qh[ks][1] = *(const uint32_t*)(smem + OFF_KHI + ((r0 + g + 8) * KST + c0)     * 2);
        qh[ks][2] = *(const uint32_t*)(smem + OFF_KHI + ((r0 + g)     * KST + c0 + 8) * 2);
        qh[ks][3] = *(const uint32_t*)(smem + OFF_KHI + ((r0 + g + 8) * KST + c0 + 8) * 2);
        ql[ks][0] = *(const uint32_t*)(smem + OFF_KLO + ((r0 + g)     * KST + c0)     * 2);
        ql[ks][1] = *(const uint32_t*)(smem + OFF_KLO + ((r0 + g + 8) * KST + c0)     * 2);
        ql[ks][2] = *(const uint32_t*)(smem + OFF_KLO + ((r0 + g)     * KST + c0 + 8) * 2);
        ql[ks][3] = *(const uint32_t*)(smem + OFF_KLO + ((r0 + g + 8) * KST + c0 + 8) * 2);
    }
    __syncthreads();

    float o[8][4];
    #pragma unroll
    for (int i = 0; i < 8; i++) { o[i][0] = o[i][1] = o[i][2] = o[i][3] = 0.f; }
    float rs0 = 0.f, rs1 = 0.f;

    for (int kt = 0; kt < NKT; kt++) {
        // ---- load + split K and V tiles ----
        const float* Kt = Kb + (size_t)(kt * BK) * HD;
        const float* Vt = Vb + (size_t)(kt * BK) * HD;
        #pragma unroll
        for (int j = 0; j < 8; j++) {
            int i = tid + j * 256;
            int r = i >> 4, c4 = (i & 15) << 2;
            float4 kv = *(const float4*)(Kt + r * HD + c4);
            split_store(smem, OFF_KHI, OFF_KLO, r * KST + c4, kv);
            float4 vv = *(const float4*)(Vt + r * HD + c4);
            split_store(smem, OFF_VHI, OFF_VLO, r * KST + c4, vv);
        }
        if (tid < BK) kms[tid] = (float)KM[b * SEQ + kt * BK + tid];
        __syncthreads();

        // ---- MMA1: S = Qhi*Khi + Qhi*Klo + Qlo*Khi   (16 n-tiles x 4 k-steps) ----
        float s[16][4];
        #pragma unroll
        for (int i = 0; i < 16; i++) { s[i][0] = s[i][1] = s[i][2] = s[i][3] = 0.f; }

        #pragma unroll
        for (int ks = 0; ks < 4; ks++) {
            #pragma unroll
            for (int h = 0; h < 2; h++) {
                uint32_t kh[8][2], kl[8][2];
                #pragma unroll
                for (int n = 0; n < 8; n++) {
                    int nr = (8 * (8 * h + n) + g) * KST + 16 * ks + 2 * t;
                    kh[n][0] = *(const uint32_t*)(smem + OFF_KHI + nr * 2);
                    kh[n][1] = *(const uint32_t*)(smem + OFF_KHI + (nr + 8) * 2);
                    kl[n][0] = *(const uint32_t*)(smem + OFF_KLO + nr * 2);
                    kl[n][1] = *(const uint32_t*)(smem + OFF_KLO + (nr + 8) * 2);
                }
                #pragma unroll
                for (int n = 0; n < 8; n++) mma16816(s[8 * h + n], qh[ks], kh[n]);
                #pragma unroll
                for (int n = 0; n < 8; n++) mma16816(s[8 * h + n], qh[ks], kl[n]);
                #pragma unroll
                for (int n = 0; n < 8; n++) mma16816(s[8 * h + n], ql[ks], kh[n]);
            }
        }

        // ---- exp + mask + rowsum + P split, then MMA2 over this k-block ----
        #pragma unroll
        for (int kk = 0; kk < 8; kk++) {
            uint32_t pa[4], pl[4];
            #pragma unroll
            for (int jj = 0; jj < 2; jj++) {
                int j = 2 * kk + jj;
                float2 km2 = *(const float2*)(kms + 8 * j + 2 * t);
                float e0 = km2.x * __expf(s[j][0] * 0.125f);
                float e1 = km2.y * __expf(s[j][1] * 0.125f);
                float e2 = km2.x * __expf(s[j][2] * 0.125f);
                float e3 = km2.y * __expf(s[j][3] * 0.125f);
                rs0 += e0 + e1;
                rs1 += e2 + e3;
                uint32_t h01 = packbf(e0, e1), h23 = packbf(e2, e3);
                pa[2 * jj]     = h01;
                pa[2 * jj + 1] = h23;
                pl[2 * jj]     = packbf(e0 - bflo(h01), e1 - bfhi(h01));
                pl[2 * jj + 1] = packbf(e2 - bflo(h23), e3 - bfhi(h23));
            }
            uint32_t vh[8][2], vl[8][2];
            const uint32_t la = lane & 15;
            #pragma unroll
            for (int dn = 0; dn < 8; dn++) {
                uint32_t ro = ((16 * kk + la) * KST + 8 * dn) * 2;
                ldm2t(vh[dn][0], vh[dn][1], sb + OFF_VHI + ro);
                ldm2t(vl[dn][0], vl[dn][1], sb + OFF_VLO + ro);
            }
            #pragma unroll
            for (int dn = 0; dn < 8; dn++) mma16816(o[dn], pa, vh[dn]);
            #pragma unroll
            for (int dn = 0; dn < 8; dn++) mma16816(o[dn], pa, vl[dn]);
            #pragma unroll
            for (int dn = 0; dn < 8; dn++) mma16816(o[dn], pl, vh[dn]);
        }
        __syncthreads();   // V/K smem reads done before next tile's stores
    }

    // ---- rowsum reduce within quad (cols split across t only) ----
    rs0 += __shfl_xor_sync(0xffffffffu, rs0, 1);
    rs0 += __shfl_xor_sync(0xffffffffu, rs0, 2);
    rs1 += __shfl_xor_sync(0xffffffffu, rs1, 1);
    rs1 += __shfl_xor_sync(0xffffffffu, rs1, 2);

    const int row0 = q0 + r0 + g, row1 = row0 + 8;
    const float inv0 = (float)QM[b * SEQ + row0] / fmaxf(rs0, 1.0f);
    const float inv1 = (float)QM[b * SEQ + row1] / fmaxf(rs1, 1.0f);

    float* Ob = O + (size_t)b * SEQ * HD;
    #pragma unroll
    for (int dn = 0; dn < 8; dn++) {
        float2 w0; w0.x = o[dn][0] * inv0; w0.y = o[dn][1] * inv0;
        *(float2*)(Ob + (size_t)row0 * HD + 8 * dn + 2 * t) = w0;
        float2 w1; w1.x = o[dn][2] * inv1; w1.y = o[dn][3] * inv1;
        *(float2*)(Ob + (size_t)row1 * HD + 8 * dn + 2 * t) = w1;
    }
}

extern "C" void kernel_launch(void* const* d_in, const int* in_sizes, int n_in,
                              void* d_out, int out_size)
{
    const float* Q  = (const float*)d_in[0];
    const float* K  = (const float*)d_in[1];
    const float* V  = (const float*)d_in[2];
    const int*   QM = (const int*)d_in[3];
    const int*   KM = (const int*)d_in[4];
    float*       O  = (float*)d_out;

    cudaFuncSetAttribute(attn77_mma, cudaFuncAttributeMaxDynamicSharedMemorySize, SMEM_BYTES);
    dim3 grid(8 * (SEQ / BQ));   // 128 blocks, one wave on 148 SMs
    attn77_mma<<<grid, 256, SMEM_BYTES>>>(Q, K, V, QM, KM, O);
}